// round 1
// baseline (speedup 1.0000x reference)
#include <cuda_runtime.h>
#include <math.h>

#define SEQ 128
#define BATCH 128
#define DIM 1024

// Scratch for the precomputed input projection xp = x @ Wx + b  : [SEQ, BATCH, DIM]
__device__ float g_xp[(size_t)SEQ * BATCH * DIM];

// ---------------------------------------------------------------------------
// Kernel 1: xp[M=16384, N=1024] = X[16384,1024] @ Wx[1024,1024] + b
// Tiles: BM=64, BN=64, BK=16; 256 threads; 4x4 register microtile.
// ---------------------------------------------------------------------------
__global__ __launch_bounds__(256) void gemm_xp_kernel(
    const float* __restrict__ X,
    const float* __restrict__ W,
    const float* __restrict__ bias)
{
    const int BM = 64, BN = 64, BK = 16;
    __shared__ float As[BK][BM];   // transposed: As[k][m]
    __shared__ float Bs[BK][BN];   // Bs[k][n]

    const int bx = blockIdx.x;     // N tile index (0..15)
    const int by = blockIdx.y;     // M tile index (0..255)
    const int tid = threadIdx.x;
    const int tr = tid >> 4;       // 0..15 row group
    const int tc = tid & 15;       // 0..15 col group
    const int row0 = by * BM;
    const int col0 = bx * BN;

    float acc[4][4] = {};

    for (int k0 = 0; k0 < DIM; k0 += BK) {
        // Load A tile: 64 rows x 16 k, one float4 per thread, store transposed.
        {
            const int m  = tid >> 2;          // 0..63
            const int kq = (tid & 3) << 2;    // 0,4,8,12
            float4 v = *reinterpret_cast<const float4*>(
                &X[(size_t)(row0 + m) * DIM + k0 + kq]);
            As[kq + 0][m] = v.x;
            As[kq + 1][m] = v.y;
            As[kq + 2][m] = v.z;
            As[kq + 3][m] = v.w;
        }
        // Load B tile: 16 k x 64 n, one float4 per thread.
        {
            const int kr = tid >> 4;          // 0..15
            const int nq = (tid & 15) << 2;   // 0..60
            float4 v = *reinterpret_cast<const float4*>(
                &W[(size_t)(k0 + kr) * DIM + col0 + nq]);
            *reinterpret_cast<float4*>(&Bs[kr][nq]) = v;
        }
        __syncthreads();

        #pragma unroll
        for (int k = 0; k < BK; k++) {
            float4 a  = *reinterpret_cast<const float4*>(&As[k][tr << 2]);
            float4 bv = *reinterpret_cast<const float4*>(&Bs[k][tc << 2]);
            float av[4] = {a.x, a.y, a.z, a.w};
            float bb[4] = {bv.x, bv.y, bv.z, bv.w};
            #pragma unroll
            for (int i = 0; i < 4; i++)
                #pragma unroll
                for (int j = 0; j < 4; j++)
                    acc[i][j] += av[i] * bb[j];
        }
        __syncthreads();
    }

    #pragma unroll
    for (int i = 0; i < 4; i++) {
        const int r = row0 + (tr << 2) + i;
        #pragma unroll
        for (int j = 0; j < 4; j++) {
            const int c = col0 + (tc << 2) + j;
            g_xp[(size_t)r * DIM + c] = acc[i][j] + bias[c];
        }
    }
}

// ---------------------------------------------------------------------------
// Kernel 2: one recurrence step
//   out[B=128, D=1024] = tanh( xp[t] + H[128,1024] @ Wh[1024,1024] )
// Tiles: BM=32, BN=32, BK=32; 256 threads; 2x2 microtile. Grid = 32 x 4 = 128.
// ---------------------------------------------------------------------------
__global__ __launch_bounds__(256) void rnn_step_kernel(
    const float* __restrict__ H,    // [BATCH, DIM] previous hidden
    const float* __restrict__ W,    // Wh [DIM, DIM]
    float* __restrict__ out,        // [BATCH, DIM] = hs[t]
    int t)
{
    const int BM = 32, BN = 32, BK = 32, PAD = 36;
    __shared__ float As[BK][PAD];   // transposed: As[k][m]
    __shared__ float Bs[BK][PAD];   // Bs[k][n]

    const int bx = blockIdx.x;      // N tile (0..31)
    const int by = blockIdx.y;      // M tile (0..3)
    const int tid = threadIdx.x;
    const int tr = tid >> 4;        // 0..15
    const int tc = tid & 15;        // 0..15
    const int row0 = by * BM;
    const int col0 = bx * BN;

    float acc[2][2] = {};

    for (int k0 = 0; k0 < DIM; k0 += BK) {
        // Load A tile: 32 rows x 32 k, one float4 per thread, transposed store.
        {
            const int m  = tid >> 3;          // 0..31
            const int kq = (tid & 7) << 2;    // 0..28
            float4 v = *reinterpret_cast<const float4*>(
                &H[(size_t)(row0 + m) * DIM + k0 + kq]);
            As[kq + 0][m] = v.x;
            As[kq + 1][m] = v.y;
            As[kq + 2][m] = v.z;
            As[kq + 3][m] = v.w;
        }
        // Load B tile: 32 k x 32 n, one float4 per thread.
        {
            const int kr = tid >> 3;          // 0..31
            const int nq = (tid & 7) << 2;    // 0..28
            float4 v = *reinterpret_cast<const float4*>(
                &W[(size_t)(k0 + kr) * DIM + col0 + nq]);
            *reinterpret_cast<float4*>(&Bs[kr][nq]) = v;   // 144B row stride -> 16B aligned
        }
        __syncthreads();

        #pragma unroll
        for (int k = 0; k < BK; k++) {
            float2 a  = *reinterpret_cast<const float2*>(&As[k][tr << 1]);
            float2 bv = *reinterpret_cast<const float2*>(&Bs[k][tc << 1]);
            acc[0][0] += a.x * bv.x;
            acc[0][1] += a.x * bv.y;
            acc[1][0] += a.y * bv.x;
            acc[1][1] += a.y * bv.y;
        }
        __syncthreads();
    }

    const float* xp_t = g_xp + (size_t)t * BATCH * DIM;
    #pragma unroll
    for (int i = 0; i < 2; i++) {
        const int r = row0 + (tr << 1) + i;
        #pragma unroll
        for (int j = 0; j < 2; j++) {
            const int c = col0 + (tc << 1) + j;
            out[(size_t)r * DIM + c] = tanhf(acc[i][j] + xp_t[(size_t)r * DIM + c]);
        }
    }
}

// ---------------------------------------------------------------------------
// Launcher: inputs in metadata order: x, h0, Wx, Wh, b
// ---------------------------------------------------------------------------
extern "C" void kernel_launch(void* const* d_in, const int* in_sizes, int n_in,
                              void* d_out, int out_size)
{
    const float* x  = (const float*)d_in[0];  // [SEQ, BATCH, DIM]
    const float* h0 = (const float*)d_in[1];  // [BATCH, DIM]
    const float* Wx = (const float*)d_in[2];  // [DIM, DIM]
    const float* Wh = (const float*)d_in[3];  // [DIM, DIM]
    const float* b  = (const float*)d_in[4];  // [DIM]
    float* out = (float*)d_out;               // [SEQ, BATCH, DIM]

    // 1) xp = x @ Wx + b   (M = SEQ*BATCH = 16384)
    {
        dim3 grid(DIM / 64, (SEQ * BATCH) / 64);  // 16 x 256
        gemm_xp_kernel<<<grid, 256>>>(x, Wx, b);
    }

    // 2) 128 sequential steps: h_t = tanh(xp[t] + h_{t-1} @ Wh)
    {
        dim3 grid(DIM / 32, BATCH / 32);          // 32 x 4 = 128 blocks
        const float* prev = h0;
        for (int t = 0; t < SEQ; t++) {
            float* ht = out + (size_t)t * BATCH * DIM;
            rnn_step_kernel<<<grid, 256>>>(prev, Wh, ht, t);
            prev = ht;
        }
    }
}